// round 5
// baseline (speedup 1.0000x reference)
#include <cuda_runtime.h>

// Problem: B=16384, D=1024.
//   j = (i + 1 + neg_idx[i]) % B
//   hinge_i = relu(1 - cos(t_i, o_i) + cos(t_j, o_i));  out = sum(hinge)/B
// HBM-bound: ~192 MiB logical reads -> target ~25 us on GB300.

#define MAX_B 16384

__device__ float g_partial[MAX_B];
__device__ int   g_idx64;

// ---------------------------------------------------------------------------
// Detect whether neg_idx buffer is int64 or int32. Values are in [0, B-1).
// If data is int32, reading as int64 combines two uniform values: lo + hi<<32,
// which exceeds B unless hi==0 (p ~ 1/16383 per sample). 128 samples -> the
// probability of misdetection is (1/16383)^128 ~ 0.
// ---------------------------------------------------------------------------
__global__ void detect_dtype_kernel(const void* __restrict__ neg, int B) {
    const long long* p = (const long long*)neg;
    int n = (B < 256 ? B / 2 : 128);   // stay within an int32 buffer of B elems
    int ok = 1;
    for (int i = 0; i < n; i++) {
        long long v = p[i];
        if (v < 0 || v >= (long long)B) { ok = 0; break; }
    }
    g_idx64 = ok;
}

__device__ __forceinline__ float warp_sum(float v) {
    v += __shfl_xor_sync(0xffffffffu, v, 16);
    v += __shfl_xor_sync(0xffffffffu, v, 8);
    v += __shfl_xor_sync(0xffffffffu, v, 4);
    v += __shfl_xor_sync(0xffffffffu, v, 2);
    v += __shfl_xor_sync(0xffffffffu, v, 1);
    return v;
}

// ---------------------------------------------------------------------------
// One block per row. 256 threads, float4 loads: each thread handles D/1024
// float4 chunks (exactly 1 for D=1024). Five simultaneous reductions.
// ---------------------------------------------------------------------------
__global__ __launch_bounds__(256)
void hinge_kernel(const float* __restrict__ outp,
                  const float* __restrict__ tgt,
                  const void*  __restrict__ neg,
                  int B, int D) {
    const int row = blockIdx.x;
    const int tid = threadIdx.x;

    long long nidx;
    if (g_idx64) nidx = ((const long long*)neg)[row];
    else         nidx = (long long)(((const int*)neg)[row]);
    long long jj = (long long)row + 1 + nidx;
    jj %= (long long)B;
    if (jj < 0) jj += B;
    const int j = (int)jj;

    const float4* __restrict__ o  = (const float4*)(outp + (size_t)row * D);
    const float4* __restrict__ t  = (const float4*)(tgt  + (size_t)row * D);
    const float4* __restrict__ tn = (const float4*)(tgt  + (size_t)j   * D);

    float d_to = 0.f, n_t = 0.f, n_o = 0.f, d_no = 0.f, n_n = 0.f;
    const int nvec = D >> 2;
    for (int i = tid; i < nvec; i += blockDim.x) {
        float4 ov = o[i];
        float4 tv = t[i];
        float4 nv = tn[i];
        d_to += tv.x * ov.x + tv.y * ov.y + tv.z * ov.z + tv.w * ov.w;
        n_t  += tv.x * tv.x + tv.y * tv.y + tv.z * tv.z + tv.w * tv.w;
        n_o  += ov.x * ov.x + ov.y * ov.y + ov.z * ov.z + ov.w * ov.w;
        d_no += nv.x * ov.x + nv.y * ov.y + nv.z * ov.z + nv.w * ov.w;
        n_n  += nv.x * nv.x + nv.y * nv.y + nv.z * nv.z + nv.w * nv.w;
    }

    // Intra-warp then cross-warp reduction of the 5 accumulators.
    d_to = warp_sum(d_to);
    n_t  = warp_sum(n_t);
    n_o  = warp_sum(n_o);
    d_no = warp_sum(d_no);
    n_n  = warp_sum(n_n);

    __shared__ float sm[5][8];
    const int wid = tid >> 5;
    const int lid = tid & 31;
    if (lid == 0) {
        sm[0][wid] = d_to;
        sm[1][wid] = n_t;
        sm[2][wid] = n_o;
        sm[3][wid] = d_no;
        sm[4][wid] = n_n;
    }
    __syncthreads();

    if (tid == 0) {
        float s0 = 0.f, s1 = 0.f, s2 = 0.f, s3 = 0.f, s4 = 0.f;
        const int nw = (blockDim.x + 31) >> 5;
        #pragma unroll
        for (int w = 0; w < 8; w++) {
            if (w < nw) {
                s0 += sm[0][w]; s1 += sm[1][w]; s2 += sm[2][w];
                s3 += sm[3][w]; s4 += sm[4][w];
            }
        }
        const float eps = 1e-6f;
        float no     = sqrtf(s2);
        float cos_p  = s0 / fmaxf(sqrtf(s1) * no, eps);
        float cos_n  = s3 / fmaxf(sqrtf(s4) * no, eps);
        float hinge  = fmaxf(0.f, 1.0f - cos_p + cos_n);
        g_partial[row] = hinge;
    }
}

// ---------------------------------------------------------------------------
// Deterministic final reduction: one block of 1024 threads over B partials.
// ---------------------------------------------------------------------------
__global__ __launch_bounds__(1024)
void reduce_kernel(float* __restrict__ out, int B) {
    const int tid = threadIdx.x;
    float s = 0.f;
    for (int i = tid; i < B; i += blockDim.x) s += g_partial[i];

    s = warp_sum(s);
    __shared__ float sm[32];
    const int wid = tid >> 5;
    const int lid = tid & 31;
    if (lid == 0) sm[wid] = s;
    __syncthreads();
    if (wid == 0) {
        float v = (lid < (blockDim.x >> 5)) ? sm[lid] : 0.f;
        v = warp_sum(v);
        if (lid == 0) out[0] = v / (float)B;
    }
}

extern "C" void kernel_launch(void* const* d_in, const int* in_sizes, int n_in,
                              void* d_out, int out_size) {
    const float* outp = (const float*)d_in[0];   // output [B, D] f32
    const float* tgt  = (const float*)d_in[1];   // target [B, D] f32
    const void*  neg  = d_in[2];                 // neg_idx [B] int64 or int32

    const int B = in_sizes[2];
    const int D = in_sizes[0] / B;

    detect_dtype_kernel<<<1, 1>>>(neg, B);
    hinge_kernel<<<B, 256>>>(outp, tgt, neg, B, D);
    reduce_kernel<<<1, 1024>>>((float*)d_out, B);
}

// round 7
// speedup vs baseline: 2.1007x; 2.1007x over previous
#include <cuda_runtime.h>

// B=16384, D=1024. j = (i + 1 + neg_idx[i]) % B
// hinge_i = relu(1 - cos(t_i,o_i) + cos(t_j,o_i)); out = mean(hinge)
// HBM-bound: >=128 MiB DRAM (output + target; gather partially L2-hit).

#define MAX_B 16384

__device__ float g_partial[MAX_B];
__device__ int   g_idx64;

// ---------------------------------------------------------------------------
// Parallel dtype detection: 128 threads each check one int64-interpreted
// value; buffer is int64 iff ALL land in [0, B). An int32 buffer read as
// int64 gives lo + hi<<32 with hi uniform in [0,B-1) -> out of range unless
// hi==0 (p ~= 1/16383 per sample); P(misdetect) = (1/16383)^128 ~= 0.
// ---------------------------------------------------------------------------
__global__ __launch_bounds__(128)
void detect_dtype_kernel(const void* __restrict__ neg, int B) {
    const long long* p = (const long long*)neg;
    int n = (B < 256 ? B / 2 : 128);           // stay inside an int32 buffer
    int ok = 1;
    if ((int)threadIdx.x < n) {
        long long v = p[threadIdx.x];
        ok = (v >= 0 && v < (long long)B);
    }
    int all_ok = __syncthreads_and(ok);
    if (threadIdx.x == 0) g_idx64 = all_ok;
}

__device__ __forceinline__ float warp_sum(float v) {
    v += __shfl_xor_sync(0xffffffffu, v, 16);
    v += __shfl_xor_sync(0xffffffffu, v, 8);
    v += __shfl_xor_sync(0xffffffffu, v, 4);
    v += __shfl_xor_sync(0xffffffffu, v, 2);
    v += __shfl_xor_sync(0xffffffffu, v, 1);
    return v;
}

// ---------------------------------------------------------------------------
// One WARP per row. 8 warps/block, no smem, no __syncthreads.
// Each lane handles D/128 = 8 float4 chunks per stream -> 24 independent
// LDG.128 per thread (high MLP). output stream uses __ldcs (no reuse,
// evict-first) to keep L2 for the target gather.
// ---------------------------------------------------------------------------
__global__ __launch_bounds__(256)
void hinge_kernel(const float* __restrict__ outp,
                  const float* __restrict__ tgt,
                  const void*  __restrict__ neg,
                  int B, int D) {
    const int warp = (blockIdx.x << 3) + (threadIdx.x >> 5);
    if (warp >= B) return;
    const int row  = warp;
    const int lane = threadIdx.x & 31;

    long long nidx;
    if (g_idx64) nidx = ((const long long*)neg)[row];
    else         nidx = (long long)(((const int*)neg)[row]);
    long long jj = ((long long)row + 1 + nidx) % (long long)B;
    if (jj < 0) jj += B;
    const int j = (int)jj;

    const float4* __restrict__ o  = (const float4*)(outp + (size_t)row * D);
    const float4* __restrict__ t  = (const float4*)(tgt  + (size_t)row * D);
    const float4* __restrict__ tn = (const float4*)(tgt  + (size_t)j   * D);

    float d_to = 0.f, n_t = 0.f, n_o = 0.f, d_no = 0.f, n_n = 0.f;
    const int nvec = D >> 2;                 // 256 float4 per row
    #pragma unroll
    for (int k = 0; k < 8; k++) {
        int i = lane + (k << 5);
        if (i < nvec) {
            float4 ov = __ldcs(&o[i]);       // streaming: evict-first
            float4 tv = t[i];
            float4 nv = tn[i];
            d_to += tv.x * ov.x + tv.y * ov.y + tv.z * ov.z + tv.w * ov.w;
            n_t  += tv.x * tv.x + tv.y * tv.y + tv.z * tv.z + tv.w * tv.w;
            n_o  += ov.x * ov.x + ov.y * ov.y + ov.z * ov.z + ov.w * ov.w;
            d_no += nv.x * ov.x + nv.y * ov.y + nv.z * ov.z + nv.w * ov.w;
            n_n  += nv.x * nv.x + nv.y * nv.y + nv.z * nv.z + nv.w * nv.w;
        }
    }

    d_to = warp_sum(d_to);
    n_t  = warp_sum(n_t);
    n_o  = warp_sum(n_o);
    d_no = warp_sum(d_no);
    n_n  = warp_sum(n_n);

    if (lane == 0) {
        const float eps = 1e-6f;
        float no    = sqrtf(n_o);
        float cos_p = d_to / fmaxf(sqrtf(n_t) * no, eps);
        float cos_n = d_no / fmaxf(sqrtf(n_n) * no, eps);
        g_partial[row] = fmaxf(0.f, 1.0f - cos_p + cos_n);
    }
}

// ---------------------------------------------------------------------------
// Deterministic final reduction: one block, float4 loads over B partials.
// ---------------------------------------------------------------------------
__global__ __launch_bounds__(1024)
void reduce_kernel(float* __restrict__ out, int B) {
    const int tid = threadIdx.x;
    const float4* p4 = (const float4*)g_partial;
    const int nv = B >> 2;
    float s = 0.f;
    for (int i = tid; i < nv; i += blockDim.x) {
        float4 v = p4[i];
        s += v.x + v.y + v.z + v.w;
    }
    // tail (B not multiple of 4)
    for (int i = (nv << 2) + tid; i < B; i += blockDim.x) s += g_partial[i];

    s = warp_sum(s);
    __shared__ float sm[32];
    const int wid = tid >> 5;
    const int lid = tid & 31;
    if (lid == 0) sm[wid] = s;
    __syncthreads();
    if (wid == 0) {
        float v = (lid < (int)(blockDim.x >> 5)) ? sm[lid] : 0.f;
        v = warp_sum(v);
        if (lid == 0) out[0] = v / (float)B;
    }
}

extern "C" void kernel_launch(void* const* d_in, const int* in_sizes, int n_in,
                              void* d_out, int out_size) {
    const float* outp = (const float*)d_in[0];   // output [B, D] f32
    const float* tgt  = (const float*)d_in[1];   // target [B, D] f32
    const void*  neg  = d_in[2];                 // neg_idx [B] int64 or int32

    const int B = in_sizes[2];
    const int D = in_sizes[0] / B;

    detect_dtype_kernel<<<1, 128>>>(neg, B);
    const int warps_per_block = 8;
    const int grid = (B + warps_per_block - 1) / warps_per_block;
    hinge_kernel<<<grid, 256>>>(outp, tgt, neg, B, D);
    reduce_kernel<<<1, 1024>>>((float*)d_out, B);
}

// round 8
// speedup vs baseline: 2.2347x; 1.0638x over previous
#include <cuda_runtime.h>

// B=16384, D=1024. j = (i + 1 + neg_idx[i]) % B
// hinge_i = relu(1 - cos(t_i,o_i) + cos(t_j,o_i)); out = mean(hinge)
// Single fused kernel: detection + per-row hinge + deterministic fixed-point
// global sum (integer atomics are associative -> replay-deterministic).

__device__ unsigned long long g_sum;    // zero at module load; self-cleaned
__device__ unsigned int       g_count;  // per call by the last block

__device__ __forceinline__ float warp_sum(float v) {
    v += __shfl_xor_sync(0xffffffffu, v, 16);
    v += __shfl_xor_sync(0xffffffffu, v, 8);
    v += __shfl_xor_sync(0xffffffffu, v, 4);
    v += __shfl_xor_sync(0xffffffffu, v, 2);
    v += __shfl_xor_sync(0xffffffffu, v, 1);
    return v;
}

// One WARP per row, 8 warps/block. Each lane: 8 float4 chunks per stream
// -> 24 independent LDG.128 (high MLP). `output` stream via __ldcs
// (no reuse; keep L2 for the target gather).
__global__ __launch_bounds__(256)
void hinge_fused_kernel(const float* __restrict__ outp,
                        const float* __restrict__ tgt,
                        const void*  __restrict__ neg,
                        float* __restrict__ out,
                        int B, int D) {
    const int wid  = threadIdx.x >> 5;
    const int lane = threadIdx.x & 31;
    const int row  = (blockIdx.x << 3) + wid;
    const bool active = (row < B);

    __shared__ int s_idx64;
    __shared__ unsigned long long s_part[8];

    // --- dtype detection (warp 0): int64 iff 16 samples all land in [0,B).
    // An int32 buffer read as int64 gives lo + hi<<32 with hi uniform in
    // [0,B-1): out-of-range unless hi==0 (p ~ 1/16383). (1/16383)^16 ~ 0.
    if (wid == 0) {
        int n = (B < 32 ? B / 2 : 16);
        int ok = 1;
        if (lane < n) {
            long long v = ((const long long*)neg)[lane];
            ok = (v >= 0 && v < (long long)B);
        }
        unsigned m = __ballot_sync(0xffffffffu, ok);
        if (lane == 0) s_idx64 = (m == 0xffffffffu);
    }
    __syncthreads();
    const int idx64 = s_idx64;

    unsigned long long fixed = 0ull;
    if (active) {
        long long nidx;
        if (idx64) nidx = ((const long long*)neg)[row];
        else       nidx = (long long)(((const int*)neg)[row]);
        long long jj = ((long long)row + 1 + nidx) % (long long)B;
        if (jj < 0) jj += B;
        const int j = (int)jj;

        const float4* __restrict__ o  = (const float4*)(outp + (size_t)row * D);
        const float4* __restrict__ t  = (const float4*)(tgt  + (size_t)row * D);
        const float4* __restrict__ tn = (const float4*)(tgt  + (size_t)j   * D);

        float d_to = 0.f, n_t = 0.f, n_o = 0.f, d_no = 0.f, n_n = 0.f;
        const int nvec = D >> 2;             // 256 float4 per row
        #pragma unroll
        for (int k = 0; k < 8; k++) {
            int i = lane + (k << 5);
            if (i < nvec) {
                float4 ov = __ldcs(&o[i]);   // streaming: evict-first
                float4 tv = t[i];
                float4 nv = tn[i];
                d_to += tv.x * ov.x + tv.y * ov.y + tv.z * ov.z + tv.w * ov.w;
                n_t  += tv.x * tv.x + tv.y * tv.y + tv.z * tv.z + tv.w * tv.w;
                n_o  += ov.x * ov.x + ov.y * ov.y + ov.z * ov.z + ov.w * ov.w;
                d_no += nv.x * ov.x + nv.y * ov.y + nv.z * ov.z + nv.w * ov.w;
                n_n  += nv.x * nv.x + nv.y * nv.y + nv.z * nv.z + nv.w * nv.w;
            }
        }

        d_to = warp_sum(d_to);
        n_t  = warp_sum(n_t);
        n_o  = warp_sum(n_o);
        d_no = warp_sum(d_no);
        n_n  = warp_sum(n_n);

        if (lane == 0) {
            const float eps = 1e-6f;
            float no    = sqrtf(n_o);
            float cos_p = d_to / fmaxf(sqrtf(n_t) * no, eps);
            float cos_n = d_no / fmaxf(sqrtf(n_n) * no, eps);
            float h     = fmaxf(0.f, 1.0f - cos_p + cos_n);
            // Q32 fixed point: h in [0,3]; sum fits in 2^49 << 2^64.
            fixed = (unsigned long long)llrint((double)h * 4294967296.0);
        }
    }

    if (lane == 0) s_part[wid] = fixed;
    __syncthreads();

    if (threadIdx.x == 0) {
        unsigned long long bs = 0ull;
        #pragma unroll
        for (int w = 0; w < 8; w++) bs += s_part[w];
        atomicAdd(&g_sum, bs);
        __threadfence();
        unsigned int c = atomicAdd(&g_count, 1u);
        if (c == gridDim.x - 1) {
            // All prior g_sum adds are visible (each fenced before its
            // g_count add). Read via atomic to force an L2 read.
            unsigned long long total = atomicAdd(&g_sum, 0ull);
            out[0] = (float)((double)total / 4294967296.0 / (double)B);
            // Self-clean for the next graph replay.
            g_sum = 0ull;
            g_count = 0u;
        }
    }
}

extern "C" void kernel_launch(void* const* d_in, const int* in_sizes, int n_in,
                              void* d_out, int out_size) {
    const float* outp = (const float*)d_in[0];   // output [B, D] f32
    const float* tgt  = (const float*)d_in[1];   // target [B, D] f32
    const void*  neg  = d_in[2];                 // neg_idx [B] int64 or int32

    const int B = in_sizes[2];
    const int D = in_sizes[0] / B;

    const int grid = (B + 7) / 8;                // one warp per row
    hinge_fused_kernel<<<grid, 256>>>(outp, tgt, neg, (float*)d_out, B, D);
}